// round 16
// baseline (speedup 1.0000x reference)
#include <cuda_runtime.h>
#include <math.h>

// FlowLenia step: SX=SY=256, C=3, K=15, DD=5, DT=0.2, SIGMA=0.65
// out = [newA (256*256*3) | newP (256*256*15)] float32

#define NX 256
#define NC 3
#define NK 15
#define NP 8
#define DTc 0.2f
#define SIGMAc 0.65f
#define MAc 4.35f
#define INV4S2 (1.0f/(4.0f*0.65f*0.65f))
#define SUPP 1.15f
#define IDX(i) ((i) + ((i) >> 4))
#define FSTR 273
#define RSTR 28
#define NBLK 256

static __device__ float2 g_fZ[2*NX*NX];      // [f][x][y]; f0 = FFT(A0+iA1), f1 = FFT(A2)
static __device__ float2 g_G [NX*NX*NP];     // [y][x][j]
static __device__ float  g_Uc[NX*NX*NC];     // [y][x][c]
static __device__ unsigned g_ctr[4];         // zero-init; reset by fused_flow each step

__device__ __forceinline__ int rev4(int i) {
    return ((i & 3) << 6) | ((i & 0xC) << 2) | ((i >> 2) & 0xC) | ((i >> 6) & 3);
}
__device__ __forceinline__ float2 cmul(float2 a, float2 b) {
    return make_float2(a.x*b.x - a.y*b.y, a.x*b.y + a.y*b.x);
}

// Grid-wide barrier. ALL NBLK blocks resident (launch_bounds(512,2), 37KB smem).
__device__ __forceinline__ void gsync(int ph) {
    __syncthreads();
    if (threadIdx.x == 0) {
        __threadfence();
        unsigned v = atomicAdd(&g_ctr[ph], 1u) + 1;
        if (v < NBLK) {
            volatile unsigned* c = &g_ctr[ph];
            while (*c < NBLK) __nanosleep(64);
        }
        __threadfence();
    }
    __syncthreads();
}

// 256-pt radix-4 DIT FFT in smem, 64 threads per FFT, input digit-reversed via IDX.
// Stage 0 specialized. ALL threads must call (block syncs inside); 'act' guards mem ops.
template<bool INV>
__device__ __forceinline__ void fftg(float2* s, const float2* tw, int t, bool act) {
    __syncthreads();
    if (act) {
        int base = t << 2;
        float2 x0 = s[IDX(base)];
        float2 t1 = s[IDX(base + 1)];
        float2 t2 = s[IDX(base + 2)];
        float2 t3 = s[IDX(base + 3)];
        float2 b0 = make_float2(x0.x + t2.x, x0.y + t2.y);
        float2 b1 = make_float2(x0.x - t2.x, x0.y - t2.y);
        float2 b2 = make_float2(t1.x + t3.x, t1.y + t3.y);
        float2 b3 = make_float2(t1.x - t3.x, t1.y - t3.y);
        float2 ib3 = INV ? make_float2(-b3.y, b3.x) : make_float2(b3.y, -b3.x);
        s[IDX(base)]     = make_float2(b0.x + b2.x, b0.y + b2.y);
        s[IDX(base + 1)] = make_float2(b1.x + ib3.x, b1.y + ib3.y);
        s[IDX(base + 2)] = make_float2(b0.x - b2.x, b0.y - b2.y);
        s[IDX(base + 3)] = make_float2(b1.x - ib3.x, b1.y - ib3.y);
    }
#pragma unroll
    for (int m = 1; m < 4; m++) {
        __syncthreads();
        if (act) {
            int q    = 1 << (2*m);
            int p    = t & (q - 1);
            int grp  = t >> (2*m);
            int base = grp*(q << 2) + p;
            int ts   = 64 >> (2*m);
            float2 w1 = tw[p*ts];
            float2 w2 = tw[2*p*ts];
            float2 w3 = tw[3*p*ts];
            if (INV) { w1.y = -w1.y; w2.y = -w2.y; w3.y = -w3.y; }
            float2 x0 = s[IDX(base)];
            float2 t1 = cmul(s[IDX(base +   q)], w1);
            float2 t2 = cmul(s[IDX(base + 2*q)], w2);
            float2 t3 = cmul(s[IDX(base + 3*q)], w3);
            float2 b0 = make_float2(x0.x + t2.x, x0.y + t2.y);
            float2 b1 = make_float2(x0.x - t2.x, x0.y - t2.y);
            float2 b2 = make_float2(t1.x + t3.x, t1.y + t3.y);
            float2 b3 = make_float2(t1.x - t3.x, t1.y - t3.y);
            float2 ib3 = INV ? make_float2(-b3.y, b3.x) : make_float2(b3.y, -b3.x);
            s[IDX(base)]        = make_float2(b0.x + b2.x, b0.y + b2.y);
            s[IDX(base +   q)]  = make_float2(b1.x + ib3.x, b1.y + ib3.y);
            s[IDX(base + 2*q)]  = make_float2(b0.x - b2.x, b0.y - b2.y);
            s[IDX(base + 3*q)]  = make_float2(b1.x - ib3.x, b1.y - ib3.y);
        }
    }
    __syncthreads();
}

// Mega kernel: fft-y -> fft-x -> mul+ifft-y -> ifft-x+growth+chansum, grid barriers.
__global__ void __launch_bounds__(512, 2)
mega(const float* __restrict__ A, const float* __restrict__ P,
     const float* __restrict__ fKr, const float* __restrict__ fKi,
     const float* __restrict__ mArr, const float* __restrict__ sArr) {
    __shared__ float2 tw[256];
    __shared__ float2 smb[NP][FSTR];
    __shared__ float  sP[NX*17];
    int tid = threadIdx.x, bid = blockIdx.x;

    for (int j = tid; j < 256; j += 512) {
        float sv, cv;
        sincospif(-(float)j * (1.0f/128.0f), &sv, &cv);
        tw[j] = make_float2(cv, sv);
    }

    // phase A: FFT along y, x = bid
    {
        int x = bid;
        bool act = tid < 128;
        int f = (tid >> 6) & 1, t = tid & 63;
        if (act) {
#pragma unroll
            for (int jj = 0; jj < 4; jj++) {
                int i = t + 64*jj;
                const float* a = A + (x*NX + i)*NC;
                smb[f][IDX(rev4(i))] = (f == 0) ? make_float2(a[0], a[1])
                                                : make_float2(a[2], 0.f);
            }
        }
        fftg<false>(smb[f], tw, t, act);
        if (act) {
#pragma unroll
            for (int jj = 0; jj < 4; jj++) {
                int i = t + 64*jj;
                g_fZ[f*NX*NX + x*NX + i] = smb[f][IDX(i)];
            }
        }
    }
    gsync(0);

    // phase B: FFT along x; f = bid&1, y0 = (bid>>1)*2
    {
        int f = bid & 1, y0 = (bid >> 1) * 2;
        int base = f*NX*NX;
        {
            int e = tid;
            int x = e >> 1, yy = e & 1;
            smb[yy][IDX(rev4(x))] = g_fZ[base + x*NX + y0 + yy];
        }
        bool act = tid < 128;
        int yl = (tid >> 6) & 1, t = tid & 63;
        fftg<false>(smb[yl], tw, t, act);
        {
            int e = tid;
            int x = e >> 1, yy = e & 1;
            g_fZ[base + x*NX + y0 + yy] = smb[yy][IDX(x)];
        }
    }
    gsync(1);

    // phase C: Hermitian unpack + mul fK + ifft along y; x = bid, 8 pairs
    {
        int x = bid, xm = (NX - x) & 255;
        float2* sZx = (float2*)sP;
        float2* sZm = sZx + NX;
        float2* sZ2 = sZm + NX;
        for (int e = tid; e < NX; e += 512) {
            sZx[e] = g_fZ[0*NX*NX + x*NX + e];
            sZm[e] = g_fZ[0*NX*NX + xm*NX + e];
            sZ2[e] = g_fZ[1*NX*NX + x*NX + e];
        }
        __syncthreads();
        for (int e = tid; e < 2048; e += 512) {
            int y = e >> 3, jj = e & 7;
            int ym = (NX - y) & 255;
            float2 Zx = sZx[y], Zm = sZm[ym];
            float2 fa[3];
            fa[0] = make_float2(0.5f*(Zx.x + Zm.x), 0.5f*(Zx.y - Zm.y));
            fa[1] = make_float2(0.5f*(Zx.y + Zm.y), 0.5f*(Zm.x - Zx.x));
            fa[2] = sZ2[y];
            int k1 = 2*jj;
            int idx = (x*NX + y)*NK;
            float2 a1 = fa[k1 % NC];
            float kr = fKr[idx + k1], ki = fKi[idx + k1];
            float2 H = make_float2(kr*a1.x - ki*a1.y, kr*a1.y + ki*a1.x);
            if (k1 + 1 < NK) {
                float2 a2 = fa[(k1+1) % NC];
                float kr2 = fKr[idx + k1 + 1], ki2 = fKi[idx + k1 + 1];
                float zr = kr2*a2.x - ki2*a2.y;
                float zi = kr2*a2.y + ki2*a2.x;
                H.x -= zi; H.y += zr;
            }
            smb[jj][IDX(rev4(y))] = H;
        }
        int j = tid >> 6, t = tid & 63;
        fftg<true>(smb[j], tw, t, true);
        for (int e = tid; e < 2048; e += 512) {
            int y = e >> 3, jj = e & 7;
            g_G[(y*NX + x)*NP + jj] = smb[jj][IDX(y)];
        }
    }
    gsync(2);

    // phase D: ifft along x + growth*P + chansum; y = bid, 8 pairs
    {
        int y = bid;
        const float2* Grow = g_G + y*NX*NP;
        for (int e = tid; e < 2048; e += 512) {
            int xx = e >> 3, jj = e & 7;
            smb[jj][IDX(rev4(xx))] = Grow[e];
        }
        for (int e = tid; e < NX*NK; e += 512) {
            int xx = e / NK, k = e - xx*NK;
            sP[xx*17 + k] = P[(xx*NX + y)*NK + k];
        }
        int j = tid >> 6, t = tid & 63;
        fftg<true>(smb[j], tw, t, true);

        int k1 = 2*j, k2 = 2*j + 1;
        float m1 = mArr[k1], s1 = sArr[k1];
        float inv1 = 1.f / (2.f * s1 * s1);
        float m2 = 0.f, inv2 = 0.f;
        if (k2 < NK) { m2 = mArr[k2]; float s2 = sArr[k2]; inv2 = 1.f / (2.f * s2 * s2); }
#pragma unroll
        for (int jj2 = 0; jj2 < 4; jj2++) {
            int xx = t + 64*jj2;
            float2 v = smb[j][IDX(xx)];
            float u1 = v.x * (1.f / 65536.f);
            float d1 = u1 - m1;
            sP[xx*17 + k1] *= (2.f * __expf(-d1*d1*inv1) - 1.f);
            if (k2 < NK) {
                float u2 = v.y * (1.f / 65536.f);
                float d2 = u2 - m2;
                sP[xx*17 + k2] *= (2.f * __expf(-d2*d2*inv2) - 1.f);
            }
        }
        __syncthreads();
        for (int e = tid; e < NX*NC; e += 512) {
            int xx = e / NC, c = e - xx*NC;
            const float* u = sP + xx*17;
            g_Uc[(y*NX + xx)*NC + c] = u[c] + u[c+3] + u[c+6] + u[c+9] + u[c+12];
        }
    }
}

// Fused sobel + mus + reintegration. 8x16 tile, 256 threads, 2 threads per output:
// thread pair (2i, 2i+1) splits the 25 taps 13/12 and merges via shfl_xor(1).
#define TXo 8
#define TYo 16
__global__ void fused_flow(const float* __restrict__ A, const float* __restrict__ P,
                           float* __restrict__ outA, float* __restrict__ outP) {
    __shared__ __align__(16) float rec[240*RSTR];
    __shared__ float sUc[14*22*3];
    __shared__ float sAs[14*22];
    int tid = threadIdx.x;                  // 256
    if (blockIdx.x == 0 && blockIdx.y == 0 && tid < 4) g_ctr[tid] = 0;  // reset barriers
    int y0 = blockIdx.x * TYo, x0 = blockIdx.y * TXo;

    for (int e = tid; e < 14*22; e += 256) {
        int i = e / 22, j = e - i*22;
        int gx = x0 - 3 + i, gy = y0 - 3 + j;
        float u0 = 0.f, u1 = 0.f, u2 = 0.f, as = 0.f;
        if (gx >= 0 && gx < NX && gy >= 0 && gy < NX) {
            int bU = (gy*NX + gx)*NC;
            u0 = g_Uc[bU]; u1 = g_Uc[bU+1]; u2 = g_Uc[bU+2];
            int bA = (gx*NX + gy)*NC;
            as = A[bA] + A[bA+1] + A[bA+2];
        }
        sUc[e*3+0] = u0; sUc[e*3+1] = u1; sUc[e*3+2] = u2;
        sAs[e] = as;
    }
    __syncthreads();

    for (int e = tid; e < 240; e += 256) {
        int i = e / 20, j = e - i*20;
        int gx = x0 - 2 + i, gy = y0 - 2 + j;
        float* r = rec + e*RSTR;
        if (gx >= 0 && gx < NX && gy >= 0 && gy < NX) {
            int si = i + 1, sj = j + 1;
            int rm = (si-1)*22 + sj, rp = (si+1)*22 + sj, r0 = si*22 + sj;
            float cg0 = (sAs[rp-1] + 2.f*sAs[rp] + sAs[rp+1])
                      - (sAs[rm-1] + 2.f*sAs[rm] + sAs[rm+1]);
            float cg1 = (sAs[rm+1] + 2.f*sAs[r0+1] + sAs[rp+1])
                      - (sAs[rm-1] + 2.f*sAs[r0-1] + sAs[rp-1]);
            int bA = (gx*NX + gy)*NC;
            float p0 = gx + 0.5f, p1 = gy + 0.5f;
#pragma unroll
            for (int c = 0; c < NC; c++) {
                float f0 = (sUc[(rp-1)*3+c] + 2.f*sUc[rp*3+c] + sUc[(rp+1)*3+c])
                         - (sUc[(rm-1)*3+c] + 2.f*sUc[rm*3+c] + sUc[(rm+1)*3+c]);
                float f1 = (sUc[(rm+1)*3+c] + 2.f*sUc[(r0+1)*3+c] + sUc[(rp+1)*3+c])
                         - (sUc[(rm-1)*3+c] + 2.f*sUc[(r0-1)*3+c] + sUc[(rp-1)*3+c]);
                float ac = A[bA + c];
                float ah = ac * 0.5f;
                float alpha = fminf(ah*ah, 1.f);
                float F0 = fminf(fmaxf(f0*(1.f-alpha) - cg0*alpha, -MAc), MAc);
                float F1 = fminf(fmaxf(f1*(1.f-alpha) - cg1*alpha, -MAc), MAc);
                r[c]   = fminf(fmaxf(p0 + DTc*F0, SIGMAc), (float)NX - SIGMAc);
                r[3+c] = fminf(fmaxf(p1 + DTc*F1, SIGMAc), (float)NX - SIGMAc);
                r[6+c] = ac;
            }
        } else {
#pragma unroll
            for (int c = 0; c < 6; c++) r[c] = -1e9f;
            r[6] = r[7] = r[8] = 0.f;
        }
    }
    for (int e = tid; e < 240*NK; e += 256) {
        int pix = e / NK, k = e - pix*NK;
        int i = pix / 20, j = pix - i*20;
        int gx = x0 - 2 + i, gy = y0 - 2 + j;
        float vv = 0.f;
        if (gx >= 0 && gx < NX && gy >= 0 && gy < NX)
            vv = P[(gx*NX + gy)*NK + k];
        rec[pix*RSTR + 9 + k] = vv;
    }
    __syncthreads();

    int h = tid & 1;                // tap-half
    int o = tid >> 1;               // output index 0..127
    int ty = o & 15, tx = o >> 4;
    int x = x0 + tx, y = y0 + ty;
    float p0 = x + 0.5f, p1 = y + 0.5f;
    float accA0 = 0.f, accA1 = 0.f, accA2 = 0.f, accW = 0.f;
    float accP[NK];
#pragma unroll
    for (int k = 0; k < NK; k++) accP[k] = 0.f;

    int t0 = h ? 13 : 0, t1 = h ? 25 : 13;
    for (int ti = t0; ti < t1; ti++) {
        int dxi = ti / 5, dyi = ti - dxi*5;      // 0..4 each
        int ridx = (tx + 4 - dxi)*20 + (ty + 4 - dyi);
        const float4* r4 = (const float4*)(rec + ridx*RSTR);
        float4 q0 = r4[0];
        float4 q1 = r4[1];
        float4 q2 = r4[2];
        float s00 = fminf(fmaxf(SUPP - fabsf(p0 - q0.x), 0.f), 1.f);
        float s01 = fminf(fmaxf(SUPP - fabsf(p0 - q0.y), 0.f), 1.f);
        float s02 = fminf(fmaxf(SUPP - fabsf(p0 - q0.z), 0.f), 1.f);
        float s10 = fminf(fmaxf(SUPP - fabsf(p1 - q0.w), 0.f), 1.f);
        float s11 = fminf(fmaxf(SUPP - fabsf(p1 - q1.x), 0.f), 1.f);
        float s12 = fminf(fmaxf(SUPP - fabsf(p1 - q1.y), 0.f), 1.f);
        float v0 = q1.z * (s00*s10*INV4S2);
        float v1 = q1.w * (s01*s11*INV4S2);
        float v2 = q2.x * (s02*s12*INV4S2);
        accA0 += v0; accA1 += v1; accA2 += v2;
        float suma = v0 + v1 + v2;
        if (suma > 0.f) {
            float w = __expf(suma) - 1.f;
            accW += w;
            accP[0] += w*q2.y; accP[1] += w*q2.z; accP[2] += w*q2.w;
            float4 q3 = r4[3], q4 = r4[4], q5 = r4[5];
            accP[3] += w*q3.x; accP[4] += w*q3.y; accP[5] += w*q3.z; accP[6] += w*q3.w;
            accP[7] += w*q4.x; accP[8] += w*q4.y; accP[9] += w*q4.z; accP[10] += w*q4.w;
            accP[11] += w*q5.x; accP[12] += w*q5.y; accP[13] += w*q5.z; accP[14] += w*q5.w;
        }
    }

    // merge the two halves (adjacent lanes, same warp)
    accA0 += __shfl_xor_sync(0xFFFFFFFFu, accA0, 1);
    accA1 += __shfl_xor_sync(0xFFFFFFFFu, accA1, 1);
    accA2 += __shfl_xor_sync(0xFFFFFFFFu, accA2, 1);
    accW  += __shfl_xor_sync(0xFFFFFFFFu, accW,  1);
#pragma unroll
    for (int k = 0; k < NK; k++)
        accP[k] += __shfl_xor_sync(0xFFFFFFFFu, accP[k], 1);

    if (h == 0) {
        int oo = x*NX + y;
        outA[oo*NC + 0] = accA0; outA[oo*NC + 1] = accA1; outA[oo*NC + 2] = accA2;
        float inv = 1.f / (accW + 1e-10f);
#pragma unroll
        for (int k = 0; k < NK; k++) outP[oo*NK + k] = accP[k] * inv;
    }
}

extern "C" void kernel_launch(void* const* d_in, const int* in_sizes, int n_in,
                              void* d_out, int out_size) {
    const float* A   = (const float*)d_in[0];
    const float* P   = (const float*)d_in[1];
    const float* fKr = (const float*)d_in[2];
    const float* fKi = (const float*)d_in[3];
    const float* m   = (const float*)d_in[4];
    const float* s   = (const float*)d_in[5];
    float* outA = (float*)d_out;
    float* outP = outA + NX*NX*NC;

    mega       <<<NBLK, 512>>>(A, P, fKr, fKi, m, s);
    fused_flow <<<dim3(16, 32), 256>>>(A, P, outA, outP);
}

// round 17
// speedup vs baseline: 1.0539x; 1.0539x over previous
#include <cuda_runtime.h>
#include <math.h>

// FlowLenia step: SX=SY=256, C=3, K=15, DD=5, DT=0.2, SIGMA=0.65
// out = [newA (256*256*3) | newP (256*256*15)] float32

#define NX 256
#define NC 3
#define NK 15
#define NP 8
#define DTc 0.2f
#define SIGMAc 0.65f
#define MAc 4.35f
#define INV4S2 (1.0f/(4.0f*0.65f*0.65f))
#define SUPP 1.15f
#define IDX(i) ((i) + ((i) >> 4))
#define FSTR 273
#define RSTR 28
#define NBLK 256
#define NREC 400            // 20x20 record halo (16x16 tile)
#define NSU  484            // 22x22 sobel halo
// arena: phases A-D use [smb | sP]; phase E uses [rec | sUc | sAs]
#define SMB_BYTES (NP*FSTR*8)                       // 17472
#define SP_BYTES  (NX*17*4)                         // 17408
#define E_BYTES   ((NREC*RSTR + NSU*3 + NSU)*4)     // 52544
#define ARENA_BYTES (E_BYTES > (SMB_BYTES+SP_BYTES) ? E_BYTES : (SMB_BYTES+SP_BYTES))

static __device__ float2 g_fZ[2*NX*NX];      // [f][x][y]; f0 = FFT(A0+iA1), f1 = FFT(A2)
static __device__ float2 g_G [NX*NX*NP];     // [y][x][j]
static __device__ float  g_Uc[NX*NX*NC];     // [y][x][c]
static __device__ unsigned long long g_ctr[4];  // monotonic barrier counters (never reset)

__device__ __forceinline__ int rev4(int i) {
    return ((i & 3) << 6) | ((i & 0xC) << 2) | ((i >> 2) & 0xC) | ((i >> 6) & 3);
}
__device__ __forceinline__ float2 cmul(float2 a, float2 b) {
    return make_float2(a.x*b.x - a.y*b.y, a.x*b.y + a.y*b.x);
}

// Grid barrier, monotonic counters: each execution adds exactly NBLK to ctr[ph];
// a block waits for the next multiple of NBLK. No reset needed across graph replays.
// All NBLK blocks resident (launch_bounds(512,2), 52.5KB smem -> 2 blocks/SM, 296>=256).
__device__ __forceinline__ void gsync(int ph) {
    __syncthreads();
    if (threadIdx.x == 0) {
        __threadfence();
        unsigned long long v = atomicAdd(&g_ctr[ph], 1ull) + 1ull;
        unsigned long long target = ((v + NBLK - 1) / NBLK) * NBLK;
        if (v != target) {
            volatile unsigned long long* c = &g_ctr[ph];
            while (*c < target) __nanosleep(64);
        }
        __threadfence();
    }
    __syncthreads();
}

// 256-pt radix-4 DIT FFT in smem, 64 threads per FFT, input digit-reversed via IDX.
// Stage 0 specialized. ALL threads must call (block syncs inside); 'act' guards mem ops.
template<bool INV>
__device__ __forceinline__ void fftg(float2* s, const float2* tw, int t, bool act) {
    __syncthreads();
    if (act) {
        int base = t << 2;
        float2 x0 = s[IDX(base)];
        float2 t1 = s[IDX(base + 1)];
        float2 t2 = s[IDX(base + 2)];
        float2 t3 = s[IDX(base + 3)];
        float2 b0 = make_float2(x0.x + t2.x, x0.y + t2.y);
        float2 b1 = make_float2(x0.x - t2.x, x0.y - t2.y);
        float2 b2 = make_float2(t1.x + t3.x, t1.y + t3.y);
        float2 b3 = make_float2(t1.x - t3.x, t1.y - t3.y);
        float2 ib3 = INV ? make_float2(-b3.y, b3.x) : make_float2(b3.y, -b3.x);
        s[IDX(base)]     = make_float2(b0.x + b2.x, b0.y + b2.y);
        s[IDX(base + 1)] = make_float2(b1.x + ib3.x, b1.y + ib3.y);
        s[IDX(base + 2)] = make_float2(b0.x - b2.x, b0.y - b2.y);
        s[IDX(base + 3)] = make_float2(b1.x - ib3.x, b1.y - ib3.y);
    }
#pragma unroll
    for (int m = 1; m < 4; m++) {
        __syncthreads();
        if (act) {
            int q    = 1 << (2*m);
            int p    = t & (q - 1);
            int grp  = t >> (2*m);
            int base = grp*(q << 2) + p;
            int ts   = 64 >> (2*m);
            float2 w1 = tw[p*ts];
            float2 w2 = tw[2*p*ts];
            float2 w3 = tw[3*p*ts];
            if (INV) { w1.y = -w1.y; w2.y = -w2.y; w3.y = -w3.y; }
            float2 x0 = s[IDX(base)];
            float2 t1 = cmul(s[IDX(base +   q)], w1);
            float2 t2 = cmul(s[IDX(base + 2*q)], w2);
            float2 t3 = cmul(s[IDX(base + 3*q)], w3);
            float2 b0 = make_float2(x0.x + t2.x, x0.y + t2.y);
            float2 b1 = make_float2(x0.x - t2.x, x0.y - t2.y);
            float2 b2 = make_float2(t1.x + t3.x, t1.y + t3.y);
            float2 b3 = make_float2(t1.x - t3.x, t1.y - t3.y);
            float2 ib3 = INV ? make_float2(-b3.y, b3.x) : make_float2(b3.y, -b3.x);
            s[IDX(base)]        = make_float2(b0.x + b2.x, b0.y + b2.y);
            s[IDX(base +   q)]  = make_float2(b1.x + ib3.x, b1.y + ib3.y);
            s[IDX(base + 2*q)]  = make_float2(b0.x - b2.x, b0.y - b2.y);
            s[IDX(base + 3*q)]  = make_float2(b1.x - ib3.x, b1.y - ib3.y);
        }
    }
    __syncthreads();
}

// ONE persistent kernel: fft-y -> fft-x -> mul+ifft-y -> ifft-x+growth+chansum ->
// sobel+mus+reintegration, with grid barriers between phases. Grid 256, block 512.
__global__ void __launch_bounds__(512, 2)
mega(const float* __restrict__ A, const float* __restrict__ P,
     const float* __restrict__ fKr, const float* __restrict__ fKi,
     const float* __restrict__ mArr, const float* __restrict__ sArr,
     float* __restrict__ outA, float* __restrict__ outP) {
    extern __shared__ __align__(16) char arena[];
    __shared__ float2 tw[256];
    float2* smb = (float2*)arena;                    // NP x FSTR (phases A-D)
    float*  sP  = (float*)(arena + SMB_BYTES);       // NX*17 (phase D; C overlays)
    int tid = threadIdx.x, bid = blockIdx.x;

    for (int j = tid; j < 256; j += 512) {
        float sv, cv;
        sincospif(-(float)j * (1.0f/128.0f), &sv, &cv);
        tw[j] = make_float2(cv, sv);
    }

    // ---- phase A: FFT along y, x = bid; packed fields (A0+iA1), A2 ----
    {
        int x = bid;
        bool act = tid < 128;
        int f = (tid >> 6) & 1, t = tid & 63;
        if (act) {
#pragma unroll
            for (int jj = 0; jj < 4; jj++) {
                int i = t + 64*jj;
                const float* a = A + (x*NX + i)*NC;
                smb[f*FSTR + IDX(rev4(i))] = (f == 0) ? make_float2(a[0], a[1])
                                                      : make_float2(a[2], 0.f);
            }
        }
        fftg<false>(smb + f*FSTR, tw, t, act);
        if (act) {
#pragma unroll
            for (int jj = 0; jj < 4; jj++) {
                int i = t + 64*jj;
                g_fZ[f*NX*NX + x*NX + i] = smb[f*FSTR + IDX(i)];
            }
        }
    }
    gsync(0);

    // ---- phase B: FFT along x; f = bid&1, y0 = (bid>>1)*2 ----
    {
        int f = bid & 1, y0 = (bid >> 1) * 2;
        int base = f*NX*NX;
        {
            int e = tid;
            int x = e >> 1, yy = e & 1;
            smb[yy*FSTR + IDX(rev4(x))] = g_fZ[base + x*NX + y0 + yy];
        }
        bool act = tid < 128;
        int yl = (tid >> 6) & 1, t = tid & 63;
        fftg<false>(smb + yl*FSTR, tw, t, act);
        {
            int e = tid;
            int x = e >> 1, yy = e & 1;
            g_fZ[base + x*NX + y0 + yy] = smb[yy*FSTR + IDX(x)];
        }
    }
    gsync(1);

    // ---- phase C: Hermitian unpack + mul fK + ifft along y; x = bid, 8 pairs ----
    {
        int x = bid, xm = (NX - x) & 255;
        float2* sZx = (float2*)sP;
        float2* sZm = sZx + NX;
        float2* sZ2 = sZm + NX;
        for (int e = tid; e < NX; e += 512) {
            sZx[e] = g_fZ[0*NX*NX + x*NX + e];
            sZm[e] = g_fZ[0*NX*NX + xm*NX + e];
            sZ2[e] = g_fZ[1*NX*NX + x*NX + e];
        }
        __syncthreads();
        for (int e = tid; e < 2048; e += 512) {
            int y = e >> 3, jj = e & 7;
            int ym = (NX - y) & 255;
            float2 Zx = sZx[y], Zm = sZm[ym];
            float2 fa[3];
            fa[0] = make_float2(0.5f*(Zx.x + Zm.x), 0.5f*(Zx.y - Zm.y));
            fa[1] = make_float2(0.5f*(Zx.y + Zm.y), 0.5f*(Zm.x - Zx.x));
            fa[2] = sZ2[y];
            int k1 = 2*jj;
            int idx = (x*NX + y)*NK;
            float2 a1 = fa[k1 % NC];
            float kr = fKr[idx + k1], ki = fKi[idx + k1];
            float2 H = make_float2(kr*a1.x - ki*a1.y, kr*a1.y + ki*a1.x);
            if (k1 + 1 < NK) {
                float2 a2 = fa[(k1+1) % NC];
                float kr2 = fKr[idx + k1 + 1], ki2 = fKi[idx + k1 + 1];
                float zr = kr2*a2.x - ki2*a2.y;
                float zi = kr2*a2.y + ki2*a2.x;
                H.x -= zi; H.y += zr;
            }
            smb[jj*FSTR + IDX(rev4(y))] = H;
        }
        int j = tid >> 6, t = tid & 63;
        fftg<true>(smb + j*FSTR, tw, t, true);
        for (int e = tid; e < 2048; e += 512) {
            int y = e >> 3, jj = e & 7;
            g_G[(y*NX + x)*NP + jj] = smb[jj*FSTR + IDX(y)];
        }
    }
    gsync(2);

    // ---- phase D: ifft along x + growth*P + chansum; y = bid, 8 pairs ----
    {
        int y = bid;
        const float2* Grow = g_G + y*NX*NP;
        for (int e = tid; e < 2048; e += 512) {
            int xx = e >> 3, jj = e & 7;
            smb[jj*FSTR + IDX(rev4(xx))] = Grow[e];
        }
        for (int e = tid; e < NX*NK; e += 512) {
            int xx = e / NK, k = e - xx*NK;
            sP[xx*17 + k] = P[(xx*NX + y)*NK + k];
        }
        int j = tid >> 6, t = tid & 63;
        fftg<true>(smb + j*FSTR, tw, t, true);

        int k1 = 2*j, k2 = 2*j + 1;
        float m1 = mArr[k1], s1 = sArr[k1];
        float inv1 = 1.f / (2.f * s1 * s1);
        float m2 = 0.f, inv2 = 0.f;
        if (k2 < NK) { m2 = mArr[k2]; float s2 = sArr[k2]; inv2 = 1.f / (2.f * s2 * s2); }
#pragma unroll
        for (int jj2 = 0; jj2 < 4; jj2++) {
            int xx = t + 64*jj2;
            float2 v = smb[j*FSTR + IDX(xx)];
            float u1 = v.x * (1.f / 65536.f);
            float d1 = u1 - m1;
            sP[xx*17 + k1] *= (2.f * __expf(-d1*d1*inv1) - 1.f);
            if (k2 < NK) {
                float u2 = v.y * (1.f / 65536.f);
                float d2 = u2 - m2;
                sP[xx*17 + k2] *= (2.f * __expf(-d2*d2*inv2) - 1.f);
            }
        }
        __syncthreads();
        for (int e = tid; e < NX*NC; e += 512) {
            int xx = e / NC, c = e - xx*NC;
            const float* u = sP + xx*17;
            g_Uc[(y*NX + xx)*NC + c] = u[c] + u[c+3] + u[c+6] + u[c+9] + u[c+12];
        }
    }
    gsync(3);

    // ---- phase E: sobel + mus + reintegration; one 16x16 tile per block ----
    {
        float* rec = (float*)arena;                 // NREC * RSTR
        float* sUc = rec + NREC*RSTR;               // NSU * 3
        float* sAs = sUc + NSU*3;                   // NSU
        int y0 = (bid & 15) * 16, x0 = (bid >> 4) * 16;

        for (int e = tid; e < NSU; e += 512) {
            int i = e / 22, j = e - i*22;
            int gx = x0 - 3 + i, gy = y0 - 3 + j;
            float u0 = 0.f, u1 = 0.f, u2 = 0.f, as = 0.f;
            if (gx >= 0 && gx < NX && gy >= 0 && gy < NX) {
                int bU = (gy*NX + gx)*NC;
                u0 = g_Uc[bU]; u1 = g_Uc[bU+1]; u2 = g_Uc[bU+2];
                int bA = (gx*NX + gy)*NC;
                as = A[bA] + A[bA+1] + A[bA+2];
            }
            sUc[e*3+0] = u0; sUc[e*3+1] = u1; sUc[e*3+2] = u2;
            sAs[e] = as;
        }
        __syncthreads();

        for (int e = tid; e < NREC; e += 512) {
            int i = e / 20, j = e - i*20;
            int gx = x0 - 2 + i, gy = y0 - 2 + j;
            float* r = rec + e*RSTR;
            if (gx >= 0 && gx < NX && gy >= 0 && gy < NX) {
                int si = i + 1, sj = j + 1;
                int rm = (si-1)*22 + sj, rp = (si+1)*22 + sj, r0 = si*22 + sj;
                float cg0 = (sAs[rp-1] + 2.f*sAs[rp] + sAs[rp+1])
                          - (sAs[rm-1] + 2.f*sAs[rm] + sAs[rm+1]);
                float cg1 = (sAs[rm+1] + 2.f*sAs[r0+1] + sAs[rp+1])
                          - (sAs[rm-1] + 2.f*sAs[r0-1] + sAs[rp-1]);
                int bA = (gx*NX + gy)*NC;
                float p0 = gx + 0.5f, p1 = gy + 0.5f;
#pragma unroll
                for (int c = 0; c < NC; c++) {
                    float f0 = (sUc[(rp-1)*3+c] + 2.f*sUc[rp*3+c] + sUc[(rp+1)*3+c])
                             - (sUc[(rm-1)*3+c] + 2.f*sUc[rm*3+c] + sUc[(rm+1)*3+c]);
                    float f1 = (sUc[(rm+1)*3+c] + 2.f*sUc[(r0+1)*3+c] + sUc[(rp+1)*3+c])
                             - (sUc[(rm-1)*3+c] + 2.f*sUc[(r0-1)*3+c] + sUc[(rp-1)*3+c]);
                    float ac = A[bA + c];
                    float ah = ac * 0.5f;
                    float alpha = fminf(ah*ah, 1.f);
                    float F0 = fminf(fmaxf(f0*(1.f-alpha) - cg0*alpha, -MAc), MAc);
                    float F1 = fminf(fmaxf(f1*(1.f-alpha) - cg1*alpha, -MAc), MAc);
                    r[c]   = fminf(fmaxf(p0 + DTc*F0, SIGMAc), (float)NX - SIGMAc);
                    r[3+c] = fminf(fmaxf(p1 + DTc*F1, SIGMAc), (float)NX - SIGMAc);
                    r[6+c] = ac;
                }
            } else {
#pragma unroll
                for (int c = 0; c < 6; c++) r[c] = -1e9f;
                r[6] = r[7] = r[8] = 0.f;
            }
        }
        for (int e = tid; e < NREC*NK; e += 512) {
            int pix = e / NK, k = e - pix*NK;
            int i = pix / 20, j = pix - i*20;
            int gx = x0 - 2 + i, gy = y0 - 2 + j;
            float vv = 0.f;
            if (gx >= 0 && gx < NX && gy >= 0 && gy < NX)
                vv = P[(gx*NX + gy)*NK + k];
            rec[pix*RSTR + 9 + k] = vv;
        }
        __syncthreads();

        if (tid < 256) {
            int ty = tid & 15, tx = tid >> 4;
            int x = x0 + tx, y = y0 + ty;
            float p0 = x + 0.5f, p1 = y + 0.5f;
            float accA0 = 0.f, accA1 = 0.f, accA2 = 0.f, accW = 0.f;
            float accP[NK];
#pragma unroll
            for (int k = 0; k < NK; k++) accP[k] = 0.f;

#pragma unroll
            for (int dx = -2; dx <= 2; dx++) {
#pragma unroll
                for (int dy = -2; dy <= 2; dy++) {
                    int ridx = (tx + 2 - dx)*20 + (ty + 2 - dy);
                    const float4* r4 = (const float4*)(rec + ridx*RSTR);
                    float4 q0 = r4[0];
                    float4 q1 = r4[1];
                    float4 q2 = r4[2];
                    float s00 = fminf(fmaxf(SUPP - fabsf(p0 - q0.x), 0.f), 1.f);
                    float s01 = fminf(fmaxf(SUPP - fabsf(p0 - q0.y), 0.f), 1.f);
                    float s02 = fminf(fmaxf(SUPP - fabsf(p0 - q0.z), 0.f), 1.f);
                    float s10 = fminf(fmaxf(SUPP - fabsf(p1 - q0.w), 0.f), 1.f);
                    float s11 = fminf(fmaxf(SUPP - fabsf(p1 - q1.x), 0.f), 1.f);
                    float s12 = fminf(fmaxf(SUPP - fabsf(p1 - q1.y), 0.f), 1.f);
                    float v0 = q1.z * (s00*s10*INV4S2);
                    float v1 = q1.w * (s01*s11*INV4S2);
                    float v2 = q2.x * (s02*s12*INV4S2);
                    accA0 += v0; accA1 += v1; accA2 += v2;
                    float suma = v0 + v1 + v2;
                    if (suma > 0.f) {
                        float w = __expf(suma) - 1.f;
                        accW += w;
                        accP[0] += w*q2.y; accP[1] += w*q2.z; accP[2] += w*q2.w;
                        float4 q3 = r4[3], q4 = r4[4], q5 = r4[5];
                        accP[3] += w*q3.x; accP[4] += w*q3.y; accP[5] += w*q3.z; accP[6] += w*q3.w;
                        accP[7] += w*q4.x; accP[8] += w*q4.y; accP[9] += w*q4.z; accP[10] += w*q4.w;
                        accP[11] += w*q5.x; accP[12] += w*q5.y; accP[13] += w*q5.z; accP[14] += w*q5.w;
                    }
                }
            }

            int oo = x*NX + y;
            outA[oo*NC + 0] = accA0; outA[oo*NC + 1] = accA1; outA[oo*NC + 2] = accA2;
            float inv = 1.f / (accW + 1e-10f);
#pragma unroll
            for (int k = 0; k < NK; k++) outP[oo*NK + k] = accP[k] * inv;
        }
    }
}

extern "C" void kernel_launch(void* const* d_in, const int* in_sizes, int n_in,
                              void* d_out, int out_size) {
    const float* A   = (const float*)d_in[0];
    const float* P   = (const float*)d_in[1];
    const float* fKr = (const float*)d_in[2];
    const float* fKi = (const float*)d_in[3];
    const float* m   = (const float*)d_in[4];
    const float* s   = (const float*)d_in[5];
    float* outA = (float*)d_out;
    float* outP = outA + NX*NX*NC;

    static bool attr_set = false;
    if (!attr_set) {
        cudaFuncSetAttribute(mega, cudaFuncAttributeMaxDynamicSharedMemorySize,
                             ARENA_BYTES);
        attr_set = true;
    }

    mega<<<NBLK, 512, ARENA_BYTES>>>(A, P, fKr, fKi, m, s, outA, outP);
}